// round 2
// baseline (speedup 1.0000x reference)
#include <cuda_runtime.h>

// Inputs (metadata order, per reference setup_inputs):
//   0: gt_rois  [1,N,5] float32  (cols 0..3 = box)
//   1: rois     [1,N,5] float32  (col 0 = batch idx, cols 1..4 = box)
//   2: labels   [N]     int32    (jnp.int64 downcast by JAX default x64-off)
//   3: means    [4]     float32
//   4: stds     [4]     float32
//   5: inside_w [4]     float32
// Output: concat of (bbox_targets[1,N,4], bbox_inside_w[1,N,4], bbox_outside_w[1,N,4])
//         = 12*N float32

__global__ __launch_bounds__(256) void rcnn_target_kernel(
    const float* __restrict__ gt,
    const float* __restrict__ rois,
    const int* __restrict__ labels,
    const float* __restrict__ means,
    const float* __restrict__ stds,
    const float* __restrict__ inw,
    float* __restrict__ out,
    int n)
{
    int i = blockIdx.x * blockDim.x + threadIdx.x;
    if (i >= n) return;

    // broadcast params (L1/L2-resident after first accesses)
    float m0 = __ldg(means + 0), m1 = __ldg(means + 1), m2 = __ldg(means + 2), m3 = __ldg(means + 3);
    float s0 = __ldg(stds + 0),  s1 = __ldg(stds + 1),  s2 = __ldg(stds + 2),  s3 = __ldg(stds + 3);
    float w0 = __ldg(inw + 0),   w1 = __ldg(inw + 1),   w2 = __ldg(inw + 2),   w3 = __ldg(inw + 3);

    const float* r = rois + 5ll * i;   // [b, x1, y1, x2, y2]
    const float* g = gt   + 5ll * i;   // [x1, y1, x2, y2, cls]

    float ex1 = r[1], ey1 = r[2], ex2 = r[3], ey2 = r[4];
    float gx1 = g[0], gy1 = g[1], gx2 = g[2], gy2 = g[3];

    float ew  = ex2 - ex1 + 1.0f;
    float eh  = ey2 - ey1 + 1.0f;
    float ecx = ex1 + 0.5f * ew;
    float ecy = ey1 + 0.5f * eh;

    float gw  = gx2 - gx1 + 1.0f;
    float gh  = gy2 - gy1 + 1.0f;
    float gcx = gx1 + 0.5f * gw;
    float gcy = gy1 + 0.5f * gh;

    float dx = (gcx - ecx) / ew;
    float dy = (gcy - ecy) / eh;
    float dw = logf(gw / ew);
    float dh = logf(gh / eh);

    bool pos = labels[i] > 0;

    float4 t;
    t.x = pos ? (dx - m0) / s0 : 0.0f;
    t.y = pos ? (dy - m1) / s1 : 0.0f;
    t.z = pos ? (dw - m2) / s2 : 0.0f;
    t.w = pos ? (dh - m3) / s3 : 0.0f;

    float4 iw;
    iw.x = pos ? w0 : 0.0f;
    iw.y = pos ? w1 : 0.0f;
    iw.z = pos ? w2 : 0.0f;
    iw.w = pos ? w3 : 0.0f;

    float4 ow;
    ow.x = (iw.x > 0.0f) ? 1.0f : 0.0f;
    ow.y = (iw.y > 0.0f) ? 1.0f : 0.0f;
    ow.z = (iw.z > 0.0f) ? 1.0f : 0.0f;
    ow.w = (iw.w > 0.0f) ? 1.0f : 0.0f;

    long long base = 4ll * i;
    long long nn4  = 4ll * n;
    reinterpret_cast<float4*>(out + base)[0]             = t;
    reinterpret_cast<float4*>(out + nn4 + base)[0]       = iw;
    reinterpret_cast<float4*>(out + 2 * nn4 + base)[0]   = ow;
}

extern "C" void kernel_launch(void* const* d_in, const int* in_sizes, int n_in,
                              void* d_out, int out_size)
{
    const float* gt     = (const float*)d_in[0];
    const float* rois   = (const float*)d_in[1];
    const int*   labels = (const int*)d_in[2];
    const float* means  = (const float*)d_in[3];
    const float* stds   = (const float*)d_in[4];
    const float* inw    = (const float*)d_in[5];
    float*       out    = (float*)d_out;

    int n = in_sizes[2];  // labels has exactly N elements

    int threads = 256;
    int blocks  = (n + threads - 1) / threads;
    rcnn_target_kernel<<<blocks, threads>>>(gt, rois, labels, means, stds, inw, out, n);
}